// round 2
// baseline (speedup 1.0000x reference)
#include <cuda_runtime.h>
#include <cstdint>
#include <cstddef>

// Shapes: B=1, H=12, S=384, V=64, D=768
// Outputs (fp32, concatenated): importance[384,384] @0, tv_norm[384,384] @147456,
// tv_std[384,384,768] @294912, resultant[384,768] @113541120

#define OFF_NORM 147456
#define OFF_TV   294912
#define OFF_RES  113541120u

// ---------------- device scratch (no allocations allowed) -------------------
__device__ float g_Tc[12*384*768];   // [h][s][d] centered*gamma per-head projection
__device__ float g_At[384*4608];     // [k][h*384+s] = attn[h,k,s]  (GEMM A)
__device__ float g_hc[384*768];      // (hidden - mean_d)*w_ln
__device__ float g_resmn[384*768];   // eps - resultant
__device__ float g_part[8*384*768];  // split-K GEMM partials
__device__ float g_biasc[768];       // (bias - mean)*w_ln
__device__ float g_inv[384];         // 1/std(pre_ln, ddof=1)

// ---------------- f32x2 helpers ---------------------------------------------
__device__ __forceinline__ unsigned long long pack2(float lo, float hi){
    unsigned long long r; asm("mov.b64 %0, {%1, %2};" : "=l"(r) : "f"(lo), "f"(hi)); return r;
}
__device__ __forceinline__ unsigned long long dup2(float a){
    unsigned long long r; asm("mov.b64 %0, {%1, %1};" : "=l"(r) : "f"(a)); return r;
}
__device__ __forceinline__ void unpack2(unsigned long long v, float& lo, float& hi){
    asm("mov.b64 {%0, %1}, %2;" : "=f"(lo), "=f"(hi) : "l"(v));
}
__device__ __forceinline__ void fma2(unsigned long long& acc, unsigned long long a, unsigned long long b){
    asm("fma.rn.f32x2 %0, %1, %2, %0;" : "+l"(acc) : "l"(a), "l"(b));
}
__device__ __forceinline__ unsigned long long add2(unsigned long long a, unsigned long long b){
    unsigned long long r; asm("add.rn.f32x2 %0, %1, %2;" : "=l"(r) : "l"(a), "l"(b)); return r;
}
__device__ __forceinline__ unsigned long long mul2(unsigned long long a, unsigned long long b){
    unsigned long long r; asm("mul.rn.f32x2 %0, %1, %2;" : "=l"(r) : "l"(a), "l"(b)); return r;
}

// ---------------- K1: row stats ----------------------------------------------
// blocks 0..383: inv_std[k] (ddof=1) from pre_ln; g_hc row. block 384: g_biasc.
__global__ void k_stats(const float* __restrict__ preln, const float* __restrict__ hidden,
                        const float* __restrict__ dbias, const float* __restrict__ wln){
    __shared__ float w1[8], w2[8], sres[2];
    int b = blockIdx.x, t = threadIdx.x, lane = t & 31, wid = t >> 5;
    if (b < 384){
        const float* row = preln + (size_t)b*768;
        float s1=0.f, s2=0.f;
        for (int d=t; d<768; d+=256){ float x=row[d]; s1+=x; s2=fmaf(x,x,s2); }
        for (int o=16;o;o>>=1){ s1+=__shfl_xor_sync(~0u,s1,o); s2+=__shfl_xor_sync(~0u,s2,o); }
        if (lane==0){ w1[wid]=s1; w2[wid]=s2; }
        __syncthreads();
        if (t==0){
            float a=0.f,c=0.f;
            #pragma unroll
            for (int j=0;j<8;j++){ a+=w1[j]; c+=w2[j]; }
            float mean = a*(1.0f/768.0f);
            float var  = (c - a*mean)*(1.0f/767.0f);
            float inv  = rsqrtf(var);
            g_inv[b]=inv; sres[0]=inv;
        }
        __syncthreads();
        const float* hr = hidden + (size_t)b*768;
        float hs=0.f;
        for (int d=t; d<768; d+=256) hs += hr[d];
        for (int o=16;o;o>>=1) hs += __shfl_xor_sync(~0u,hs,o);
        __syncthreads();  // w1 reuse
        if (lane==0) w1[wid]=hs;
        __syncthreads();
        if (t==0){
            float a=0.f;
            #pragma unroll
            for (int j=0;j<8;j++) a+=w1[j];
            sres[1]=a*(1.0f/768.0f);
        }
        __syncthreads();
        float hmean = sres[1];
        for (int d=t; d<768; d+=256)
            g_hc[(size_t)b*768+d] = (hr[d]-hmean)*wln[d];
    } else {
        float s=0.f;
        for (int d=t; d<768; d+=256) s += dbias[d];
        for (int o=16;o;o>>=1) s += __shfl_xor_sync(~0u,s,o);
        if (lane==0) w1[wid]=s;
        __syncthreads();
        if (t==0){
            float a=0.f;
            #pragma unroll
            for (int j=0;j<8;j++) a+=w1[j];
            sres[0]=a*(1.0f/768.0f);
        }
        __syncthreads();
        float mean = sres[0];
        for (int d=t; d<768; d+=256) g_biasc[d] = (dbias[d]-mean)*wln[d];
    }
}

// ---------------- K2: Tc[h][s][d] = (value_h @ W_h^T  centered) * w_ln -------
__global__ __launch_bounds__(256) void k_tc(const float* __restrict__ value,
                                            const float* __restrict__ dw,
                                            const float* __restrict__ wln){
    __shared__ float val[12*64];
    __shared__ float T[12*768];
    __shared__ float means[12];
    int s0 = blockIdx.x*12, h = blockIdx.y, t = threadIdx.x;
    if (t < 192)
        ((float4*)val)[t] = ((const float4*)(value + ((size_t)h*384 + s0)*64))[t];
    __syncthreads();
    const unsigned long long* val2 = (const unsigned long long*)val;
    #pragma unroll 1
    for (int g=0; g<3; g++){
        int d = g*256 + t;
        unsigned long long w2[32];
        const unsigned long long* wr = (const unsigned long long*)(dw + ((size_t)d*12 + h)*64);
        #pragma unroll
        for (int i=0;i<32;i++) w2[i]=wr[i];
        #pragma unroll 1
        for (int s=0;s<12;s++){
            unsigned long long acc = 0ull;
            #pragma unroll
            for (int i=0;i<32;i++) fma2(acc, w2[i], val2[s*32+i]);
            float lo,hi; unpack2(acc,lo,hi);
            T[s*768 + d] = lo + hi;
        }
    }
    __syncthreads();
    int w = t>>5, l = t&31;
    for (int s=w; s<12; s+=8){
        float sum=0.f;
        for (int i=l; i<768; i+=32) sum += T[s*768+i];
        for (int o=16;o;o>>=1) sum += __shfl_xor_sync(~0u,sum,o);
        if (l==0) means[s] = sum*(1.0f/768.0f);
    }
    __syncthreads();
    #pragma unroll 1
    for (int g=0; g<3; g++){
        int d = g*256+t; float wl = wln[d];
        #pragma unroll
        for (int s=0;s<12;s++)
            g_Tc[((size_t)h*384 + s0 + s)*768 + d] = (T[s*768+d]-means[s])*wl;
    }
}

// ---------------- K3: At[k][h*384+s] = attn[h][k][s]  (row copies) -----------
__global__ void k_at(const float* __restrict__ attn){
    int k = blockIdx.x, t = threadIdx.x;
    float4* dst = (float4*)(g_At + (size_t)k*4608);
    for (int idx=t; idx<1152; idx+=256){
        int h = idx/96, j = idx - h*96;
        dst[h*96 + j] = ((const float4*)(attn + ((size_t)h*384 + k)*384))[j];
    }
}

// ---------------- K4: split-K SGEMM  C[384,768] = At[384,4608] @ Tc ----------
__global__ __launch_bounds__(256) void k_gemm(){
    __shared__ float As[16*132];
    __shared__ float Bs[16*128];
    int m0 = blockIdx.x*128, n0 = blockIdx.y*128, z = blockIdx.z;
    int K0 = z*576;
    int t = threadIdx.x;
    int ty = t>>4, tx = t&15;
    unsigned long long acc[8][4];
    #pragma unroll
    for (int i=0;i<8;i++)
        #pragma unroll
        for (int j=0;j<4;j++) acc[i][j]=0ull;
    for (int ks=0; ks<36; ks++){
        int kb = K0 + ks*16;
        #pragma unroll
        for (int rep=0; rep<2; rep++){
            int idx = t + rep*256;
            int r = idx>>2, c = (idx&3)*4;
            float4 a4 = *(const float4*)(g_At + (size_t)(m0+r)*4608 + kb + c);
            As[(c+0)*132+r]=a4.x; As[(c+1)*132+r]=a4.y;
            As[(c+2)*132+r]=a4.z; As[(c+3)*132+r]=a4.w;
            int rb = idx>>5, cb = (idx&31)*4;
            *(float4*)&Bs[rb*128+cb] = *(const float4*)(g_Tc + (size_t)(kb+rb)*768 + n0 + cb);
        }
        __syncthreads();
        #pragma unroll
        for (int kk=0; kk<16; kk++){
            float4 a1 = *(float4*)&As[kk*132 + ty*8];
            float4 a2 = *(float4*)&As[kk*132 + ty*8 + 4];
            float4 b1 = *(float4*)&Bs[kk*128 + tx*8];
            float4 b2 = *(float4*)&Bs[kk*128 + tx*8 + 4];
            unsigned long long bv0=pack2(b1.x,b1.y), bv1=pack2(b1.z,b1.w);
            unsigned long long bv2=pack2(b2.x,b2.y), bv3=pack2(b2.z,b2.w);
            float av[8]={a1.x,a1.y,a1.z,a1.w,a2.x,a2.y,a2.z,a2.w};
            #pragma unroll
            for (int i=0;i<8;i++){
                unsigned long long ad = dup2(av[i]);
                fma2(acc[i][0],ad,bv0); fma2(acc[i][1],ad,bv1);
                fma2(acc[i][2],ad,bv2); fma2(acc[i][3],ad,bv3);
            }
        }
        __syncthreads();
    }
    #pragma unroll
    for (int i=0;i<8;i++){
        int row = m0 + ty*8 + i;
        float* dst = g_part + ((size_t)z*384 + row)*768 + n0 + tx*8;
        #pragma unroll
        for (int j=0;j<4;j++) *(unsigned long long*)(dst + j*2) = acc[i][j];
    }
}

// ---------------- K5: resultant + resmn --------------------------------------
__global__ void k_res(const float* __restrict__ lnb, float* __restrict__ out_res){
    int k = blockIdx.x;
    float inv = g_inv[k];
    for (int d=threadIdx.x; d<768; d+=256){
        float s = 0.f;
        #pragma unroll
        for (int z=0; z<8; z++) s += g_part[((size_t)z*384 + k)*768 + d];
        float ao = s + g_hc[(size_t)k*768 + d] + g_biasc[d];
        float r  = ao*inv + lnb[d];
        out_res[(size_t)k*768 + d] = r;
        g_resmn[(size_t)k*768 + d] = 1e-6f - r;
    }
}

// ---------------- K6: main fused kernel --------------------------------------
// block = (s, k-half). 384 thr = 2 groups x 192 (each thread owns 4 d).
// tv_std written once; norm & importance reduced in-flight.
__global__ __launch_bounds__(384) void k_main(const float* __restrict__ attn,
                                              float* __restrict__ out){
    __shared__ float cs[192*12];
    __shared__ float pn[192*6];
    __shared__ float pa[192*6];
    int s = blockIdx.x;
    int kbase = blockIdx.y*192;
    int t = threadIdx.x;

    // stage attn coefficients * inv_std[k]
    for (int idx=t; idx<2304; idx+=384){
        int kk = idx/12, h = idx - kk*12;
        int k = kbase + kk;
        cs[idx] = attn[(size_t)h*147456 + (size_t)k*384 + s] * g_inv[k];
    }

    int grp = t/192;
    int tt  = t - grp*192;
    int d0  = tt*4;

    // register-resident Tc[h][d0..d0+3]
    unsigned long long tca[12], tcb[12];
    #pragma unroll
    for (int h=0; h<12; h++){
        ulonglong2 v = *(const ulonglong2*)(g_Tc + ((size_t)h*384 + s)*768 + d0);
        tca[h]=v.x; tcb[h]=v.y;
    }
    unsigned long long hca, hcb;
    {
        ulonglong2 v = *(const ulonglong2*)(g_hc + (size_t)s*768 + d0);
        unsigned long long iv = dup2(g_inv[s]);
        hca = mul2(v.x, iv); hcb = mul2(v.y, iv);
    }
    __syncthreads();

    int wgrp = (t>>5) % 6;
    float* out_tv = out + OFF_TV;
    const unsigned long long MSK = 0x7FFFFFFF7FFFFFFFULL;

    int kk0 = grp*96, kk1 = kk0 + 96;
    ulonglong2 rv = *(const ulonglong2*)(g_resmn + (size_t)(kbase+kk0)*768 + d0);
    #pragma unroll 1
    for (int kk=kk0; kk<kk1; kk++){
        int k = kbase + kk;
        int knext = kbase + (kk+1 < kk1 ? kk+1 : kk);
        ulonglong2 rvn = *(const ulonglong2*)(g_resmn + (size_t)knext*768 + d0);

        float4 c0 = *(const float4*)&cs[kk*12];
        float4 c1 = *(const float4*)&cs[kk*12+4];
        float4 c2 = *(const float4*)&cs[kk*12+8];
        float cf[12] = {c0.x,c0.y,c0.z,c0.w, c1.x,c1.y,c1.z,c1.w, c2.x,c2.y,c2.z,c2.w};

        unsigned long long acc0, acc1;
        if (k==s){ acc0 = hca; acc1 = hcb; } else { acc0 = 0ull; acc1 = 0ull; }
        #pragma unroll
        for (int h=0; h<12; h++){
            unsigned long long ad = dup2(cf[h]);
            fma2(acc0, ad, tca[h]);
            fma2(acc1, ad, tcb[h]);
        }

        // store tv_std (16B per thread, contiguous per warp)
        ulonglong2 st; st.x=acc0; st.y=acc1;
        *(ulonglong2*)(out_tv + ((size_t)k*384 + s)*768 + d0) = st;

        // norm^2 partial
        unsigned long long n2 = 0ull;
        fma2(n2, acc0, acc0);
        fma2(n2, acc1, acc1);
        // |tv_std - resultant + eps| partial
        unsigned long long df0 = add2(acc0, rv.x) & MSK;
        unsigned long long df1 = add2(acc1, rv.y) & MSK;
        unsigned long long aa  = add2(df0, df1);

        float nlo,nhi,alo,ahi;
        unpack2(n2,nlo,nhi); unpack2(aa,alo,ahi);
        float sn = nlo+nhi, sa = alo+ahi;
        #pragma unroll
        for (int o=16;o;o>>=1){
            sn += __shfl_xor_sync(~0u,sn,o);
            sa += __shfl_xor_sync(~0u,sa,o);
        }
        if ((t&31)==0){ pn[kk*6+wgrp]=sn; pa[kk*6+wgrp]=sa; }
        rv = rvn;
    }
    __syncthreads();

    if (t < 192){
        int kk = t, k = kbase + kk;
        float sn=0.f, sa=0.f;
        #pragma unroll
        for (int j=0;j<6;j++){ sn += pn[kk*6+j]; sa += pa[kk*6+j]; }
        out[(size_t)k*384 + s]            = -sa;        // importance
        out[OFF_NORM + (size_t)k*384 + s] = sqrtf(sn);  // tv_norm
    }
}

// ---------------- launch ------------------------------------------------------
extern "C" void kernel_launch(void* const* d_in, const int* in_sizes, int n_in,
                              void* d_out, int out_size){
    (void)in_sizes; (void)n_in; (void)out_size;
    const float* value  = (const float*)d_in[0];
    const float* attn   = (const float*)d_in[1];
    const float* hidden = (const float*)d_in[2];
    const float* preln  = (const float*)d_in[3];
    const float* dw     = (const float*)d_in[4];
    const float* dbias  = (const float*)d_in[5];
    const float* wln    = (const float*)d_in[6];
    const float* lnb    = (const float*)d_in[7];
    float* out = (float*)d_out;

    k_stats<<<385, 256>>>(preln, hidden, dbias, wln);
    k_tc<<<dim3(32,12), 256>>>(value, dw, wln);
    k_at<<<384, 256>>>(attn);
    k_gemm<<<dim3(3,6,8), 256>>>();
    k_res<<<384, 256>>>(lnb, out + OFF_RES);
    k_main<<<dim3(384,2), 384>>>(attn, out);
}